// round 7
// baseline (speedup 1.0000x reference)
#include <cuda_runtime.h>
#include <cuda_fp16.h>
#include <cstdint>

// ============================================================================
// ScaledDotProductAttention  B=32, S=2048, D=128, fp32 io, int32 mask.
// Base-ISA (sm_103 target) flash attention, two kernels:
//  1) prepass: fp32 -> fp16 conversion of Q (prescaled by 1/sqrt(D)*log2e),
//     K, V into __device__ scratch.
//  2) attn: cp.async double-buffered K/V/MASK tiles, mma.sync m16n8k16,
//     single-pass fp16 scores (fp32 accum), no-max softmax (masked -> p = 0),
//     O in registers, one final normalization.
//  R7: iteration restructured into 4 software-pipelined stages (16 keys each):
//  MMA1(s+1) issues before softmax(s)/MMA2(s), hiding ex2/ldsm latency under
//  tensor work. Same math, same totals, reordered instruction stream.
// ============================================================================

static constexpr int B_  = 32;
static constexpr int S_  = 2048;
static constexpr int D_  = 128;
static constexpr int TQ  = 64;       // query rows per CTA (16 per warp, 4 warps)
static constexpr int BC  = 64;       // keys per iteration
static constexpr int NIT = S_ / BC;  // 32

static constexpr int NELEM = B_ * S_ * D_;   // 8388608

// fp16 smem tiles: padded rows, 136 halves = 272 B stride (conflict-free ldmatrix)
static constexpr int ROWH = D_ + 8;
static constexpr int RBYT = ROWH * 2;        // 272
static constexpr int SZ_T  = BC * RBYT;      // 17408

static constexpr int OFF_KB0 = 0;
static constexpr int OFF_VB0 = OFF_KB0 + SZ_T;
static constexpr int OFF_KB1 = OFF_VB0 + SZ_T;
static constexpr int OFF_VB1 = OFF_KB1 + SZ_T;
static constexpr int OFF_MB0 = OFF_VB1 + SZ_T;
static constexpr int OFF_MB1 = OFF_MB0 + SZ_T;
static constexpr int SMEM_TOTAL = OFF_MB1 + SZ_T;   // 104448 -> 2 CTAs/SM

// fp16 scratch (device globals: allocation-free scratch)
__device__ __half g_qh[NELEM];
__device__ __half g_kh[NELEM];
__device__ __half g_vh[NELEM];

// ---------------------------------------------------------------------------
__device__ __forceinline__ uint32_t smem_u32(const void* p) {
    uint32_t a;
    asm("{ .reg .u64 t; cvta.to.shared.u64 t, %1; cvt.u32.u64 %0, t; }"
        : "=r"(a) : "l"(p));
    return a;
}

__device__ __forceinline__ void ldsm4(uint32_t* r, uint32_t a) {
    asm volatile("ldmatrix.sync.aligned.m8n8.x4.shared.b16 {%0,%1,%2,%3}, [%4];"
        : "=r"(r[0]), "=r"(r[1]), "=r"(r[2]), "=r"(r[3]) : "r"(a));
}

__device__ __forceinline__ void ldsm4t(uint32_t* r, uint32_t a) {
    asm volatile("ldmatrix.sync.aligned.m8n8.x4.trans.shared.b16 {%0,%1,%2,%3}, [%4];"
        : "=r"(r[0]), "=r"(r[1]), "=r"(r[2]), "=r"(r[3]) : "r"(a));
}

__device__ __forceinline__ void mma16816(float* c, const uint32_t* a,
                                         const uint32_t* b) {
    asm volatile(
        "mma.sync.aligned.m16n8k16.row.col.f32.f16.f16.f32 "
        "{%0,%1,%2,%3}, {%4,%5,%6,%7}, {%8,%9}, {%0,%1,%2,%3};"
        : "+f"(c[0]), "+f"(c[1]), "+f"(c[2]), "+f"(c[3])
        : "r"(a[0]), "r"(a[1]), "r"(a[2]), "r"(a[3]), "r"(b[0]), "r"(b[1]));
}

__device__ __forceinline__ void cpasync16(uint32_t dst, const void* src) {
    asm volatile("cp.async.cg.shared.global [%0], [%1], 16;"
        :: "r"(dst), "l"(src));
}
#define CP_COMMIT()  asm volatile("cp.async.commit_group;" ::: "memory")
#define CP_WAIT1()   asm volatile("cp.async.wait_group 1;" ::: "memory")

__device__ __forceinline__ float ex2f(float x) {
    float r;
    asm("ex2.approx.ftz.f32 %0, %1;" : "=f"(r) : "f"(x));
    return r;
}

__device__ __forceinline__ uint32_t packh2(float a, float b) {
    __half2 h = __halves2half2(__float2half_rn(a), __float2half_rn(b));
    return *reinterpret_cast<uint32_t*>(&h);
}

// ---------------------------------------------------------------------------
// Pre-pass: fp32 -> fp16 scratch. Q prescaled by (1/sqrt(D))*log2(e).
// ---------------------------------------------------------------------------
__global__ void __launch_bounds__(256)
prepass_kernel(const float* __restrict__ Qp, const float* __restrict__ Kp,
               const float* __restrict__ Vp) {
    const float SC = 0.08838834764831845f * 1.4426950408889634f;
    const int N4 = NELEM / 4;
    uint2* qh4 = (uint2*)g_qh;
    uint2* kh4 = (uint2*)g_kh;
    uint2* vh4 = (uint2*)g_vh;
    for (int i = blockIdx.x * blockDim.x + threadIdx.x; i < N4;
         i += gridDim.x * blockDim.x) {
        float4 q = ((const float4*)Qp)[i];
        uint2 qq;
        qq.x = packh2(q.x * SC, q.y * SC);
        qq.y = packh2(q.z * SC, q.w * SC);
        qh4[i] = qq;

        float4 k = ((const float4*)Kp)[i];
        uint2 kk;
        kk.x = packh2(k.x, k.y);
        kk.y = packh2(k.z, k.w);
        kh4[i] = kk;

        float4 v = ((const float4*)Vp)[i];
        uint2 vv;
        vv.x = packh2(v.x, v.y);
        vv.y = packh2(v.z, v.w);
        vh4[i] = vv;
    }
}

// ---------------------------------------------------------------------------
// Main attention kernel: 128 threads (4 warps), TQ=64 rows, 2 CTAs/SM.
// ---------------------------------------------------------------------------
__device__ __forceinline__ void issue_tile16(uint32_t dst_base, const __half* src,
                                             int tid) {
    #pragma unroll
    for (int r = 0; r < 8; r++) {
        int i = tid + 128 * r;
        int row = i >> 4;
        int c   = i & 15;
        cpasync16(dst_base + row * RBYT + c * 16, (const char*)src + i * 16);
    }
}

// mask tile: 64 rows x 64 int32 from gmem (row stride S_*4) -> smem (272B rows)
__device__ __forceinline__ void issue_mask16(uint32_t dst_base, const int* src,
                                             int tid) {
    #pragma unroll
    for (int r = 0; r < 8; r++) {
        int i = tid + 128 * r;
        int row = i >> 4;
        int c   = i & 15;
        cpasync16(dst_base + row * RBYT + c * 16,
                  (const char*)(src + (size_t)row * S_) + c * 16);
    }
}

__global__ void __launch_bounds__(128, 2)
attn_kernel(const int* __restrict__ Mk, float* __restrict__ Out) {
    extern __shared__ __align__(128) char smem[];
    const uint32_t sb = smem_u32(smem);
    const int tid  = threadIdx.x;
    const int lane = tid & 31;
    const int w    = tid >> 5;
    const int b    = blockIdx.y;
    const int q0   = blockIdx.x * TQ;
    const size_t bS = (size_t)b * S_;

    const int* m_base = Mk + (bS + q0) * S_;   // mask rows for this q-tile

    // ---- prologue: {K,V,M} tile0 (group 0), {K,V,M} tile1 (group 1) ----
    issue_tile16(sb + OFF_KB0, g_kh + bS * D_, tid);
    issue_tile16(sb + OFF_VB0, g_vh + bS * D_, tid);
    issue_mask16(sb + OFF_MB0, m_base, tid);
    CP_COMMIT();
    issue_tile16(sb + OFF_KB1, g_kh + (bS + BC) * D_, tid);
    issue_tile16(sb + OFF_VB1, g_vh + (bS + BC) * D_, tid);
    issue_mask16(sb + OFF_MB1, m_base + BC, tid);
    CP_COMMIT();

    // ---- resident Q A-fragments loaded straight from gmem (canonical
    //      m16n8k16 A layout), overlapped with the cp.async prologue ----
    const int fr = w * 16 + (lane >> 2);       // fragment rows fr, fr+8
    const int fc = (lane & 3) * 2;
    uint32_t qh[8][4];
    {
        const __half* q_base = g_qh + (bS + q0) * D_;
        const __half* qr0 = q_base + (size_t)fr * D_ + fc;
        const __half* qr1 = qr0 + 8 * D_;
        #pragma unroll
        for (int kc = 0; kc < 8; kc++) {
            qh[kc][0] = *(const uint32_t*)(qr0 + kc * 16);
            qh[kc][1] = *(const uint32_t*)(qr1 + kc * 16);
            qh[kc][2] = *(const uint32_t*)(qr0 + kc * 16 + 8);
            qh[kc][3] = *(const uint32_t*)(qr1 + kc * 16 + 8);
        }
    }

    // ---- per-thread ldmatrix address components (K and V tiles) ----
    const uint32_t k_row  = (uint32_t)(((lane >> 4) & 1) * 8 + (lane & 7)) * RBYT;
    const uint32_t k_col  = (uint32_t)((lane >> 3) & 1) * 16;
    const uint32_t v_row  = (uint32_t)(((lane >> 3) & 1) * 8 + (lane & 7)) * RBYT;
    const uint32_t v_col  = (uint32_t)((lane >> 4) & 1) * 16;

    // mask smem offsets for this thread's two fragment rows
    const uint32_t m_off0 = (uint32_t)fr * RBYT + (uint32_t)fc * 4;
    const uint32_t m_off1 = m_off0 + 8 * RBYT;

    float O[16][4];
    #pragma unroll
    for (int i = 0; i < 16; i++)
        { O[i][0] = 0.f; O[i][1] = 0.f; O[i][2] = 0.f; O[i][3] = 0.f; }
    float sum0 = 0.f, sum1 = 0.f;

    // ======================= main loop over key tiles =======================
    for (int t = 0; t < NIT; t++) {
        CP_WAIT1();          // tile t resident (tile t+1 may be in flight)
        __syncthreads();

        const uint32_t kb = sb + ((t & 1) ? OFF_KB1 : OFF_KB0);
        const uint32_t vb = sb + ((t & 1) ? OFF_VB1 : OFF_VB0);
        const uint32_t mb = sb + ((t & 1) ? OFF_MB1 : OFF_MB0);

        float    Sv[8][4];
        uint32_t P[4][4];
        int2     mr0[8], mr1[8];

        // ---- stage helpers (compile-time s; fully unrolled) ----
        #define MASK_LD(s)                                                    \
            { _Pragma("unroll")                                               \
              for (int jj = 2*(s); jj < 2*(s) + 2; jj++) {                    \
                asm volatile("ld.shared.v2.u32 {%0,%1}, [%2];"                \
                    : "=r"(mr0[jj].x), "=r"(mr0[jj].y)                        \
                    : "r"(mb + m_off0 + jj * 32));                            \
                asm volatile("ld.shared.v2.u32 {%0,%1}, [%2];"                \
                    : "=r"(mr1[jj].x), "=r"(mr1[jj].y)                        \
                    : "r"(mb + m_off1 + jj * 32));                            \
              } }

        #define MMA1_STAGE(s)                                                 \
            { Sv[2*(s)][0]=0.f; Sv[2*(s)][1]=0.f;                             \
              Sv[2*(s)][2]=0.f; Sv[2*(s)][3]=0.f;                             \
              Sv[2*(s)+1][0]=0.f; Sv[2*(s)+1][1]=0.f;                         \
              Sv[2*(s)+1][2]=0.f; Sv[2*(s)+1][3]=0.f;                         \
              _Pragma("unroll")                                               \
              for (int kc = 0; kc < 8; kc++) {                                \
                uint32_t kh[4];                                               \
                uint32_t off = (uint32_t)(s) * 16 * RBYT + k_row              \
                             + kc * 32 + k_col;                               \
                ldsm4(kh, kb + off);                                          \
                mma16816(Sv[2*(s)],     qh[kc], &kh[0]);                      \
                mma16816(Sv[2*(s)+1],   qh[kc], &kh[2]);                      \
              } }

        #define SOFTMAX_STAGE(s)                                              \
            { _Pragma("unroll")                                               \
              for (int jj = 2*(s); jj < 2*(s) + 2; jj++) {                    \
                float p0 = mr0[jj].x ? ex2f(Sv[jj][0]) : 0.f;                 \
                float p1 = mr0[jj].y ? ex2f(Sv[jj][1]) : 0.f;                 \
                float p2 = mr1[jj].x ? ex2f(Sv[jj][2]) : 0.f;                 \
                float p3 = mr1[jj].y ? ex2f(Sv[jj][3]) : 0.f;                 \
                sum0 += p0 + p1;                                              \
                sum1 += p2 + p3;                                              \
                P[s][(jj & 1) * 2 + 0] = packh2(p0, p1);                      \
                P[s][(jj & 1) * 2 + 1] = packh2(p2, p3);                      \
              } }

        #define MMA2_STAGE(s)                                                 \
            { _Pragma("unroll")                                               \
              for (int nd = 0; nd < 8; nd++) {                                \
                uint32_t vbr[4];                                              \
                uint32_t off = (uint32_t)(s) * 16 * RBYT + v_row              \
                             + nd * 32 + v_col;                               \
                ldsm4t(vbr, vb + off);                                        \
                mma16816(O[2 * nd],     P[s], &vbr[0]);                       \
                mma16816(O[2 * nd + 1], P[s], &vbr[2]);                       \
              } }

        // ---- skewed pipeline: MMA1(s+1) issues before softmax/MMA2(s) ----
        MASK_LD(0); MMA1_STAGE(0);
        MASK_LD(1); MMA1_STAGE(1); SOFTMAX_STAGE(0); MMA2_STAGE(0);
        MASK_LD(2); MMA1_STAGE(2); SOFTMAX_STAGE(1); MMA2_STAGE(1);
        MASK_LD(3); MMA1_STAGE(3); SOFTMAX_STAGE(2); MMA2_STAGE(2);
        SOFTMAX_STAGE(3); MMA2_STAGE(3);

        #undef MASK_LD
        #undef MMA1_STAGE
        #undef SOFTMAX_STAGE
        #undef MMA2_STAGE

        __syncthreads();     // all warps done with buffer (t&1)
        if (t + 2 < NIT) {
            issue_tile16(kb, g_kh + (bS + (size_t)(t + 2) * BC) * D_, tid);
            issue_tile16(vb, g_vh + (bS + (size_t)(t + 2) * BC) * D_, tid);
            issue_mask16(mb, m_base + (t + 2) * BC, tid);
        }
        CP_COMMIT();         // always commit: keeps group accounting uniform
    }

    // ---- rowsum reduce across the 4 lanes of each row group ----
    sum0 += __shfl_xor_sync(0xFFFFFFFFu, sum0, 1);
    sum0 += __shfl_xor_sync(0xFFFFFFFFu, sum0, 2);
    sum1 += __shfl_xor_sync(0xFFFFFFFFu, sum1, 1);
    sum1 += __shfl_xor_sync(0xFFFFFFFFu, sum1, 2);
    const float inv0 = 1.0f / sum0;
    const float inv1 = 1.0f / sum1;

    // ---- write O ----
    float* o0 = Out + (bS + q0 + fr) * D_ + fc;
    float* o1 = o0 + 8 * D_;
    #pragma unroll
    for (int nd = 0; nd < 16; nd++) {
        float2 a, c;
        a.x = O[nd][0] * inv0; a.y = O[nd][1] * inv0;
        c.x = O[nd][2] * inv1; c.y = O[nd][3] * inv1;
        *(float2*)(o0 + nd * 8) = a;
        *(float2*)(o1 + nd * 8) = c;
    }
}

// ---------------------------------------------------------------------------
extern "C" void kernel_launch(void* const* d_in, const int* in_sizes, int n_in,
                              void* d_out, int out_size) {
    const float* Q = (const float*)d_in[0];
    const float* K = (const float*)d_in[1];
    const float* V = (const float*)d_in[2];
    const int* mask = (const int*)d_in[3];
    float* out = (float*)d_out;

    prepass_kernel<<<2048, 256>>>(Q, K, V);

    cudaFuncSetAttribute(attn_kernel,
                         cudaFuncAttributeMaxDynamicSharedMemorySize, SMEM_TOTAL);
    dim3 grid(S_ / TQ, B_);
    attn_kernel<<<grid, 128, SMEM_TOTAL>>>(mask, out);
}

// round 8
// speedup vs baseline: 1.3871x; 1.3871x over previous
#include <cuda_runtime.h>
#include <cuda_fp16.h>
#include <cstdint>

// ============================================================================
// ScaledDotProductAttention  B=32, S=2048, D=128, fp32 io, int32 mask.
// Base-ISA (sm_103 target) flash attention, two kernels:
//  1) prepass: fp32 -> fp16 conversion of Q (prescaled by 1/sqrt(D)*log2e),
//     K, V into __device__ scratch.
//  2) attn: producer-warp cp.async pipeline (mbarrier full/free handshakes),
//     4 consumer warps run mma.sync m16n8k16; single-pass fp16 scores (fp32
//     accum), no-max softmax (masked -> p = 0), O in registers, one final
//     normalization. Consumer body identical to R6 (R7 reorder reverted).
// ============================================================================

static constexpr int B_  = 32;
static constexpr int S_  = 2048;
static constexpr int D_  = 128;
static constexpr int TQ  = 64;       // query rows per CTA (16 per consumer warp)
static constexpr int BC  = 64;       // keys per iteration
static constexpr int NIT = S_ / BC;  // 32

static constexpr int NELEM = B_ * S_ * D_;   // 8388608

// fp16 smem tiles: padded rows, 136 halves = 272 B stride (conflict-free ldmatrix)
static constexpr int ROWH = D_ + 8;
static constexpr int RBYT = ROWH * 2;        // 272
static constexpr int SZ_T  = BC * RBYT;      // 17408

static constexpr int OFF_KB0 = 0;
static constexpr int OFF_VB0 = OFF_KB0 + SZ_T;
static constexpr int OFF_KB1 = OFF_VB0 + SZ_T;
static constexpr int OFF_VB1 = OFF_KB1 + SZ_T;
static constexpr int OFF_MB0 = OFF_VB1 + SZ_T;
static constexpr int OFF_MB1 = OFF_MB0 + SZ_T;
static constexpr int OFF_BAR = OFF_MB1 + SZ_T;       // 104448
// bars: FULL0 +0, FULL1 +8, FREE0 +16, FREE1 +24
static constexpr int SMEM_TOTAL = OFF_BAR + 32;      // 104480 -> 2 CTAs/SM

// fp16 scratch (device globals: allocation-free scratch)
__device__ __half g_qh[NELEM];
__device__ __half g_kh[NELEM];
__device__ __half g_vh[NELEM];

// ---------------------------------------------------------------------------
__device__ __forceinline__ uint32_t smem_u32(const void* p) {
    uint32_t a;
    asm("{ .reg .u64 t; cvta.to.shared.u64 t, %1; cvt.u32.u64 %0, t; }"
        : "=r"(a) : "l"(p));
    return a;
}

__device__ __forceinline__ void ldsm4(uint32_t* r, uint32_t a) {
    asm volatile("ldmatrix.sync.aligned.m8n8.x4.shared.b16 {%0,%1,%2,%3}, [%4];"
        : "=r"(r[0]), "=r"(r[1]), "=r"(r[2]), "=r"(r[3]) : "r"(a));
}

__device__ __forceinline__ void ldsm4t(uint32_t* r, uint32_t a) {
    asm volatile("ldmatrix.sync.aligned.m8n8.x4.trans.shared.b16 {%0,%1,%2,%3}, [%4];"
        : "=r"(r[0]), "=r"(r[1]), "=r"(r[2]), "=r"(r[3]) : "r"(a));
}

__device__ __forceinline__ void mma16816(float* c, const uint32_t* a,
                                         const uint32_t* b) {
    asm volatile(
        "mma.sync.aligned.m16n8k16.row.col.f32.f16.f16.f32 "
        "{%0,%1,%2,%3}, {%4,%5,%6,%7}, {%8,%9}, {%0,%1,%2,%3};"
        : "+f"(c[0]), "+f"(c[1]), "+f"(c[2]), "+f"(c[3])
        : "r"(a[0]), "r"(a[1]), "r"(a[2]), "r"(a[3]), "r"(b[0]), "r"(b[1]));
}

__device__ __forceinline__ void cpasync16(uint32_t dst, const void* src) {
    asm volatile("cp.async.cg.shared.global [%0], [%1], 16;"
        :: "r"(dst), "l"(src));
}

#define MBAR_INIT(addr, cnt) \
    asm volatile("mbarrier.init.shared.b64 [%0], %1;" \
        :: "r"((uint32_t)(addr)), "r"((uint32_t)(cnt)) : "memory")

#define MBAR_ARRIVE(addr) \
    asm volatile("{\n\t.reg .b64 s;\n\tmbarrier.arrive.shared.b64 s, [%0];\n\t}" \
        :: "r"((uint32_t)(addr)) : "memory")

#define CP_MBAR_ARRIVE(addr) \
    asm volatile("cp.async.mbarrier.arrive.noinc.shared.b64 [%0];" \
        :: "r"((uint32_t)(addr)) : "memory")

#define MBAR_WAIT(addr, parity) do {                                          \
    uint32_t _m = (uint32_t)(addr);                                           \
    uint32_t _p = (uint32_t)(parity);                                         \
    uint32_t _done;                                                           \
    asm volatile(                                                             \
        "{\n\t.reg .pred p;\n\t"                                              \
        "mbarrier.try_wait.parity.acquire.cta.shared::cta.b64 p, [%1], %2;\n\t" \
        "selp.b32 %0, 1, 0, p;\n\t}"                                          \
        : "=r"(_done) : "r"(_m), "r"(_p) : "memory");                         \
    if (!_done) {                                                             \
        asm volatile(                                                         \
            "{\n\t.reg .pred P1;\n\t"                                         \
            "WAIT_LOOP_%=:\n\t"                                               \
            "mbarrier.try_wait.parity.acquire.cta.shared::cta.b64 P1, [%0], %1, 0x989680;\n\t" \
            "@P1 bra.uni WAIT_DONE_%=;\n\t"                                   \
            "bra.uni WAIT_LOOP_%=;\n\t"                                       \
            "WAIT_DONE_%=:\n\t}"                                              \
            :: "r"(_m), "r"(_p) : "memory");                                  \
    }                                                                         \
} while (0)

__device__ __forceinline__ float ex2f(float x) {
    float r;
    asm("ex2.approx.ftz.f32 %0, %1;" : "=f"(r) : "f"(x));
    return r;
}

__device__ __forceinline__ uint32_t packh2(float a, float b) {
    __half2 h = __halves2half2(__float2half_rn(a), __float2half_rn(b));
    return *reinterpret_cast<uint32_t*>(&h);
}

// ---------------------------------------------------------------------------
// Pre-pass: fp32 -> fp16 scratch. Q prescaled by (1/sqrt(D))*log2(e).
// ---------------------------------------------------------------------------
__global__ void __launch_bounds__(256)
prepass_kernel(const float* __restrict__ Qp, const float* __restrict__ Kp,
               const float* __restrict__ Vp) {
    const float SC = 0.08838834764831845f * 1.4426950408889634f;
    const int N4 = NELEM / 4;
    uint2* qh4 = (uint2*)g_qh;
    uint2* kh4 = (uint2*)g_kh;
    uint2* vh4 = (uint2*)g_vh;
    for (int i = blockIdx.x * blockDim.x + threadIdx.x; i < N4;
         i += gridDim.x * blockDim.x) {
        float4 q = ((const float4*)Qp)[i];
        uint2 qq;
        qq.x = packh2(q.x * SC, q.y * SC);
        qq.y = packh2(q.z * SC, q.w * SC);
        qh4[i] = qq;

        float4 k = ((const float4*)Kp)[i];
        uint2 kk;
        kk.x = packh2(k.x, k.y);
        kk.y = packh2(k.z, k.w);
        kh4[i] = kk;

        float4 v = ((const float4*)Vp)[i];
        uint2 vv;
        vv.x = packh2(v.x, v.y);
        vv.y = packh2(v.z, v.w);
        vh4[i] = vv;
    }
}

// ---------------------------------------------------------------------------
// Main attention kernel: 160 threads = 4 consumer warps + 1 producer warp.
// ---------------------------------------------------------------------------
__global__ void __launch_bounds__(160, 2)
attn_kernel(const int* __restrict__ Mk, float* __restrict__ Out) {
    extern __shared__ __align__(128) char smem[];
    const uint32_t sb = smem_u32(smem);
    const int tid  = threadIdx.x;
    const int lane = tid & 31;
    const int w    = tid >> 5;
    const int b    = blockIdx.y;
    const int q0   = blockIdx.x * TQ;
    const size_t bS = (size_t)b * S_;

    const uint32_t FULL0 = sb + OFF_BAR + 0,  FULL1 = sb + OFF_BAR + 8;
    const uint32_t FREE0 = sb + OFF_BAR + 16, FREE1 = sb + OFF_BAR + 24;

    if (tid == 0) {
        MBAR_INIT(FULL0, 32);  MBAR_INIT(FULL1, 32);
        MBAR_INIT(FREE0, 128); MBAR_INIT(FREE1, 128);
    }
    __syncthreads();

    const int* m_base = Mk + (bS + q0) * S_;   // mask rows for this q-tile

    // ======================= PRODUCER warp (w == 4) =======================
    if (w == 4) {
        const uint32_t kdst[2] = {sb + OFF_KB0, sb + OFF_KB1};
        const uint32_t vdst[2] = {sb + OFF_VB0, sb + OFF_VB1};
        const uint32_t mdst[2] = {sb + OFF_MB0, sb + OFF_MB1};

        // fill(t, buf): 32 chunks each of K, V, M per thread
        #define FILL_TILE(t, bb)                                              \
        {                                                                     \
            const char* ks = (const char*)(g_kh + (bS + (size_t)(t) * BC) * D_); \
            const char* vs = (const char*)(g_vh + (bS + (size_t)(t) * BC) * D_); \
            const int*  ms = m_base + (t) * BC;                               \
            _Pragma("unroll 4")                                               \
            for (int r = 0; r < 32; r++) {                                    \
                int i = lane + 32 * r;                                        \
                int row = i >> 4;                                             \
                int c   = i & 15;                                             \
                uint32_t so = row * RBYT + c * 16;                            \
                cpasync16(kdst[bb] + so, ks + i * 16);                        \
                cpasync16(vdst[bb] + so, vs + i * 16);                        \
                cpasync16(mdst[bb] + so,                                      \
                          (const char*)(ms + (size_t)row * S_) + c * 16);     \
            }                                                                 \
        }

        FILL_TILE(0, 0); CP_MBAR_ARRIVE(FULL0);
        FILL_TILE(1, 1); CP_MBAR_ARRIVE(FULL1);
        for (int t = 2; t < NIT; t++) {
            int bb = t & 1;
            MBAR_WAIT(bb ? FREE1 : FREE0, ((t - 2) >> 1) & 1);
            FILL_TILE(t, bb);
            CP_MBAR_ARRIVE(bb ? FULL1 : FULL0);
        }
        #undef FILL_TILE
        return;
    }

    // ======================= CONSUMER warps (w 0..3) =======================
    // resident Q A-fragments loaded straight from gmem (canonical m16n8k16 A)
    const int fr = w * 16 + (lane >> 2);       // fragment rows fr, fr+8
    const int fc = (lane & 3) * 2;
    uint32_t qh[8][4];
    {
        const __half* q_base = g_qh + (bS + q0) * D_;
        const __half* qr0 = q_base + (size_t)fr * D_ + fc;
        const __half* qr1 = qr0 + 8 * D_;
        #pragma unroll
        for (int kc = 0; kc < 8; kc++) {
            qh[kc][0] = *(const uint32_t*)(qr0 + kc * 16);
            qh[kc][1] = *(const uint32_t*)(qr1 + kc * 16);
            qh[kc][2] = *(const uint32_t*)(qr0 + kc * 16 + 8);
            qh[kc][3] = *(const uint32_t*)(qr1 + kc * 16 + 8);
        }
    }

    // per-thread ldmatrix address components (K and V tiles)
    const uint32_t k_row  = (uint32_t)(((lane >> 4) & 1) * 8 + (lane & 7)) * RBYT;
    const uint32_t k_col  = (uint32_t)((lane >> 3) & 1) * 16;
    const uint32_t v_row  = (uint32_t)(((lane >> 3) & 1) * 8 + (lane & 7)) * RBYT;
    const uint32_t v_col  = (uint32_t)((lane >> 4) & 1) * 16;

    // mask smem offsets for this thread's two fragment rows
    const uint32_t m_off0 = (uint32_t)fr * RBYT + (uint32_t)fc * 4;
    const uint32_t m_off1 = m_off0 + 8 * RBYT;

    float O[16][4];
    #pragma unroll
    for (int i = 0; i < 16; i++)
        { O[i][0] = 0.f; O[i][1] = 0.f; O[i][2] = 0.f; O[i][3] = 0.f; }
    float sum0 = 0.f, sum1 = 0.f;

    for (int t = 0; t < NIT; t++) {
        const int bb = t & 1;
        MBAR_WAIT(bb ? FULL1 : FULL0, (t >> 1) & 1);

        const uint32_t kb = sb + (bb ? OFF_KB1 : OFF_KB0);
        const uint32_t vb = sb + (bb ? OFF_VB1 : OFF_VB0);
        const uint32_t mb = sb + (bb ? OFF_MB1 : OFF_MB0);

        // ---- MMA1: S = Q*K^T, single-pass fp16 (fp32 accumulate) ----
        float Sv[8][4];
        #pragma unroll
        for (int i = 0; i < 8; i++)
            { Sv[i][0] = 0.f; Sv[i][1] = 0.f; Sv[i][2] = 0.f; Sv[i][3] = 0.f; }

        #pragma unroll
        for (int kc = 0; kc < 8; kc++) {
            #pragma unroll
            for (int np = 0; np < 4; np++) {
                uint32_t kh[4];
                uint32_t off = (uint32_t)np * 16 * RBYT + k_row + kc * 32 + k_col;
                ldsm4(kh, kb + off);
                mma16816(Sv[2 * np],     qh[kc], &kh[0]);
                mma16816(Sv[2 * np + 1], qh[kc], &kh[2]);
            }
        }

        // ---- mask (from smem) + exp2, pack P as A-fragments ----
        uint32_t P[4][4];
        #pragma unroll
        for (int j = 0; j < 8; j++) {
            int2 m0, m1;
            asm volatile("ld.shared.v2.u32 {%0,%1}, [%2];"
                : "=r"(m0.x), "=r"(m0.y) : "r"(mb + m_off0 + j * 32));
            asm volatile("ld.shared.v2.u32 {%0,%1}, [%2];"
                : "=r"(m1.x), "=r"(m1.y) : "r"(mb + m_off1 + j * 32));
            float p0 = m0.x ? ex2f(Sv[j][0]) : 0.f;
            float p1 = m0.y ? ex2f(Sv[j][1]) : 0.f;
            float p2 = m1.x ? ex2f(Sv[j][2]) : 0.f;
            float p3 = m1.y ? ex2f(Sv[j][3]) : 0.f;
            sum0 += p0 + p1;
            sum1 += p2 + p3;
            P[j >> 1][(j & 1) * 2 + 0] = packh2(p0, p1);
            P[j >> 1][(j & 1) * 2 + 1] = packh2(p2, p3);
        }

        // ---- MMA2: O += P * V  (V B-frags via ldmatrix.trans) ----
        #pragma unroll
        for (int kk = 0; kk < 4; kk++) {
            #pragma unroll
            for (int nd = 0; nd < 8; nd++) {
                uint32_t vbr[4];
                uint32_t off = (uint32_t)kk * 16 * RBYT + v_row + nd * 32 + v_col;
                ldsm4t(vbr, vb + off);
                mma16816(O[2 * nd],     P[kk], &vbr[0]);
                mma16816(O[2 * nd + 1], P[kk], &vbr[2]);
            }
        }

        MBAR_ARRIVE(bb ? FREE1 : FREE0);   // buffer free for producer
    }

    // ---- rowsum reduce across the 4 lanes of each row group ----
    sum0 += __shfl_xor_sync(0xFFFFFFFFu, sum0, 1);
    sum0 += __shfl_xor_sync(0xFFFFFFFFu, sum0, 2);
    sum1 += __shfl_xor_sync(0xFFFFFFFFu, sum1, 1);
    sum1 += __shfl_xor_sync(0xFFFFFFFFu, sum1, 2);
    const float inv0 = 1.0f / sum0;
    const float inv1 = 1.0f / sum1;

    // ---- write O ----
    float* o0 = Out + (bS + q0 + fr) * D_ + fc;
    float* o1 = o0 + 8 * D_;
    #pragma unroll
    for (int nd = 0; nd < 16; nd++) {
        float2 a, c;
        a.x = O[nd][0] * inv0; a.y = O[nd][1] * inv0;
        c.x = O[nd][2] * inv1; c.y = O[nd][3] * inv1;
        *(float2*)(o0 + nd * 8) = a;
        *(float2*)(o1 + nd * 8) = c;
    }
}

// ---------------------------------------------------------------------------
extern "C" void kernel_launch(void* const* d_in, const int* in_sizes, int n_in,
                              void* d_out, int out_size) {
    const float* Q = (const float*)d_in[0];
    const float* K = (const float*)d_in[1];
    const float* V = (const float*)d_in[2];
    const int* mask = (const int*)d_in[3];
    float* out = (float*)d_out;

    prepass_kernel<<<2048, 256>>>(Q, K, V);

    cudaFuncSetAttribute(attn_kernel,
                         cudaFuncAttributeMaxDynamicSharedMemorySize, SMEM_TOTAL);
    dim3 grid(S_ / TQ, B_);
    attn_kernel<<<grid, 160, SMEM_TOTAL>>>(mask, out);
}